// round 3
// baseline (speedup 1.0000x reference)
#include <cuda_runtime.h>
#include <cstdint>

#define BB 4
#define CC 192
#define NN 8192
#define KK 16
#define COUT 192
#define TWOC 384
#define TILE_N 64
#define THREADS 256
#define SREL_S 68                 // rel row stride in floats (mult of 4 -> 16B rows)
#define CHUNK 24
#define NCHUNK (TWOC / CHUNK)     // 16
#define WPAD 25

#define SREL_BYTES (CC * SREL_S * 4)          // 52224
#define WSD_OFF    SREL_BYTES
#define WSD_BYTES  (COUT * WPAD * 8)          // 38400
#define IDX_OFF    (WSD_OFF + WSD_BYTES)      // 90624
#define SMEM_TOTAL (IDX_OFF + 2 * TILE_N * KK * 4)  // 98816

typedef unsigned long long ull;

// x transposed to [B, N, C]: a gathered node-column is 768B contiguous.
__device__ float g_xt[(size_t)BB * NN * CC];

// ---------------------------------------------------------------------------
// Kernel 1: transpose x [B, C, N] -> g_xt [B, N, C]
// ---------------------------------------------------------------------------
__global__ void transpose_kernel(const float* __restrict__ x) {
    __shared__ float tile[32][33];
    int b  = blockIdx.z;
    int n0 = blockIdx.x * 32;
    int c0 = blockIdx.y * 32;
    int tx = threadIdx.x, ty = threadIdx.y;
    const float* in  = x    + (size_t)b * CC * NN;
    float*      outp = g_xt + (size_t)b * NN * CC;
#pragma unroll
    for (int i = 0; i < 32; i += 8)
        tile[ty + i][tx] = in[(size_t)(c0 + ty + i) * NN + n0 + tx];
    __syncthreads();
#pragma unroll
    for (int i = 0; i < 32; i += 8)
        outp[(size_t)(n0 + ty + i) * CC + c0 + tx] = tile[tx][ty + i];
}

// ---------------------------------------------------------------------------
// Kernel 2: fused gather + max-relative + 1x1 conv + bias + relu
// 256 threads, 64-node tile, 2 CTAs/SM.
// y = [xs ; rel]: xs half read straight from global x (already [c][n]),
// rel half built in smem [c][n] (stride 68).
// ---------------------------------------------------------------------------
__global__ __launch_bounds__(THREADS, 2)
void fused_kernel(const float* __restrict__ x, const int* __restrict__ edge,
                  const float* __restrict__ W, const float* __restrict__ bias,
                  float* __restrict__ out) {
    extern __shared__ char smem[];
    float*  srel = (float*)smem;                 // rel: [192 c][68] (n in 0..63)
    float2* wsd  = (float2*)(smem + WSD_OFF);    // W chunk duplicated: [o][25] {w,w}
    ull*    wsq  = (ull*)wsd;
    float*  stg  = (float*)wsd;                  // epilogue staging (aliases wsd)
    int*    sj   = (int*)(smem + IDX_OFF);       // neighbors j
    int*    si   = sj + TILE_N * KK;             // centers i

    const int tid = threadIdx.x;
    const int bid = blockIdx.x;
    const int b   = bid >> 7;
    const int n0  = (bid & 127) * TILE_N;

    // ---- edge indices (coalesced) ----
    {
        const int* ej = edge + ((size_t)b * NN + n0) * KK;
        const int* ei = edge + ((size_t)(BB + b) * NN + n0) * KK;
        for (int t = tid; t < TILE_N * KK; t += THREADS) {
            sj[t] = ej[t];
            si[t] = ei[t];
        }
    }
    __syncthreads();

    // ---- gather + max-relative into srel[c][n] ----
    const float* bx  = g_xt + (size_t)b * NN * CC;
    const int wid  = tid >> 5;
    const int lane = tid & 31;
    const int cb   = lane * 2;
    for (int nn = wid; nn < TILE_N; nn += 8) {
        float2 r0 = make_float2(-3.0e38f, -3.0e38f), r1 = r0, r2 = r0;
        const int* sjn = sj + nn * KK;
        const int* sin = si + nn * KK;
#pragma unroll 4
        for (int k = 0; k < KK; k++) {
            const float* pj = bx + (size_t)sjn[k] * CC + cb;
            const float* pi = bx + (size_t)sin[k] * CC + cb;
            float2 a0 = *(const float2*)(pj);       float2 c0v = *(const float2*)(pi);
            float2 a1 = *(const float2*)(pj + 64);  float2 c1v = *(const float2*)(pi + 64);
            float2 a2 = *(const float2*)(pj + 128); float2 c2v = *(const float2*)(pi + 128);
            r0.x = fmaxf(r0.x, a0.x - c0v.x); r0.y = fmaxf(r0.y, a0.y - c0v.y);
            r1.x = fmaxf(r1.x, a1.x - c1v.x); r1.y = fmaxf(r1.y, a1.y - c1v.y);
            r2.x = fmaxf(r2.x, a2.x - c2v.x); r2.y = fmaxf(r2.y, a2.y - c2v.y);
        }
        srel[(cb)       * SREL_S + nn] = r0.x;
        srel[(cb + 1)   * SREL_S + nn] = r0.y;
        srel[(cb + 64)  * SREL_S + nn] = r1.x;
        srel[(cb + 65)  * SREL_S + nn] = r1.y;
        srel[(cb + 128) * SREL_S + nn] = r2.x;
        srel[(cb + 129) * SREL_S + nn] = r2.y;
    }

    // ---- GEMM: thread (oi, ni): 6 output rows x 8 nodes (two groups of 4) ----
    const int oi = tid >> 3;
    const int ni = tid & 7;

    float bv[6];
#pragma unroll
    for (int m = 0; m < 6; m++) bv[m] = bias[oi * 6 + m];

    ull acc[6][4];
#pragma unroll
    for (int m = 0; m < 6; m++)
#pragma unroll
        for (int p = 0; p < 4; p++) acc[m][p] = 0ULL;

    const ull*   wp = wsq + oi * 6 * WPAD;
    const float* xb = x + (size_t)b * CC * NN + n0 + ni * 4;

    // part 1: c in [0,192), y = xs from global x (coalesced LDG.128, L2/L1 hit)
    for (int ch = 0; ch < NCHUNK / 2; ch++) {
        const float* wsrc = W + ch * CHUNK;
        for (int t = tid; t < COUT * CHUNK; t += THREADS) {
            int o = t / CHUNK, k = t - o * CHUNK;
            float v = wsrc[(size_t)o * TWOC + k];
            wsd[o * WPAD + k] = make_float2(v, v);
        }
        __syncthreads();
        const float* xc = xb + (size_t)ch * CHUNK * NN;
#pragma unroll
        for (int kk = 0; kk < CHUNK; kk++) {
            longlong2 q0 = *(const longlong2*)(xc + (size_t)kk * NN);
            longlong2 q1 = *(const longlong2*)(xc + (size_t)kk * NN + 32);
            ull y2[4] = { (ull)q0.x, (ull)q0.y, (ull)q1.x, (ull)q1.y };
#pragma unroll
            for (int m = 0; m < 6; m++) {
                ull w = wp[m * WPAD + kk];
#pragma unroll
                for (int p = 0; p < 4; p++)
                    asm("fma.rn.f32x2 %0, %1, %2, %3;"
                        : "=l"(acc[m][p]) : "l"(w), "l"(y2[p]), "l"(acc[m][p]));
            }
        }
        __syncthreads();
    }

    // part 2: c in [192,384), y = rel from smem (LDS.128, conflict-free)
    for (int ch = NCHUNK / 2; ch < NCHUNK; ch++) {
        const float* wsrc = W + ch * CHUNK;
        for (int t = tid; t < COUT * CHUNK; t += THREADS) {
            int o = t / CHUNK, k = t - o * CHUNK;
            float v = wsrc[(size_t)o * TWOC + k];
            wsd[o * WPAD + k] = make_float2(v, v);
        }
        __syncthreads();
        const longlong2* yr =
            (const longlong2*)(srel + (size_t)(ch - NCHUNK / 2) * CHUNK * SREL_S + ni * 4);
#pragma unroll
        for (int kk = 0; kk < CHUNK; kk++) {
            longlong2 q0 = yr[kk * (SREL_S / 4)];
            longlong2 q1 = yr[kk * (SREL_S / 4) + 8];   // +32 floats
            ull y2[4] = { (ull)q0.x, (ull)q0.y, (ull)q1.x, (ull)q1.y };
#pragma unroll
            for (int m = 0; m < 6; m++) {
                ull w = wp[m * WPAD + kk];
#pragma unroll
                for (int p = 0; p < 4; p++)
                    asm("fma.rn.f32x2 %0, %1, %2, %3;"
                        : "=l"(acc[m][p]) : "l"(w), "l"(y2[p]), "l"(acc[m][p]));
            }
        }
        __syncthreads();
    }

    // ---- epilogue: bias + relu, restage for coalesced float4 stores ----
    const size_t outbase = (size_t)b * COUT * NN + n0;
#pragma unroll 1
    for (int m = 0; m < 6; m++) {
        __syncthreads();
#pragma unroll
        for (int p = 0; p < 4; p++) {
            float lo, hi;
            asm("mov.b64 {%0, %1}, %2;" : "=f"(lo), "=f"(hi) : "l"(acc[m][p]));
            lo = fmaxf(lo + bv[m], 0.0f);
            hi = fmaxf(hi + bv[m], 0.0f);
            int node = (p >> 1) * 32 + ni * 4 + (p & 1) * 2;
            stg[oi * 68 + node]     = lo;
            stg[oi * 68 + node + 1] = hi;
        }
        __syncthreads();
        int r   = tid >> 3;
        int col = (tid & 7) * 8;
        float4 q0 = *(const float4*)(stg + r * 68 + col);
        float4 q1 = *(const float4*)(stg + r * 68 + col + 4);
        float* op = out + outbase + (size_t)(r * 6 + m) * NN + col;
        *(float4*)(op)     = q0;
        *(float4*)(op + 4) = q1;
    }
}

// ---------------------------------------------------------------------------
// Launch
// ---------------------------------------------------------------------------
extern "C" void kernel_launch(void* const* d_in, const int* in_sizes, int n_in,
                              void* d_out, int out_size) {
    const float* x    = (const float*)d_in[0];
    const int*   edge = (const int*)d_in[2];
    const float* W    = (const float*)d_in[3];
    const float* bias = (const float*)d_in[4];
    float*       out  = (float*)d_out;

    cudaFuncSetAttribute(fused_kernel, cudaFuncAttributeMaxDynamicSharedMemorySize,
                         SMEM_TOTAL);

    transpose_kernel<<<dim3(NN / 32, CC / 32, BB), dim3(32, 8)>>>(x);
    fused_kernel<<<BB * (NN / TILE_N), THREADS, SMEM_TOTAL>>>(x, edge, W, bias, out);
}

// round 4
// speedup vs baseline: 1.8165x; 1.8165x over previous
#include <cuda_runtime.h>
#include <cstdint>

#define BB 4
#define CC 192
#define NN 8192
#define KK 16
#define COUT 192
#define TWOC 384

typedef unsigned long long ull;

// Scratch: x transposed to [B, N, C] (gathered node-column = 768B contiguous),
// and rel output in [B, C, N] (GEMM-friendly, coalesced).
__device__ float g_xt[(size_t)BB * NN * CC];
__device__ float g_rel[(size_t)BB * CC * NN];

// ---------------------------------------------------------------------------
// Kernel 1: transpose x [B, C, N] -> g_xt [B, N, C]
// ---------------------------------------------------------------------------
__global__ void transpose_kernel(const float* __restrict__ x) {
    __shared__ float tile[32][33];
    int b  = blockIdx.z;
    int n0 = blockIdx.x * 32;
    int c0 = blockIdx.y * 32;
    int tx = threadIdx.x, ty = threadIdx.y;
    const float* in  = x    + (size_t)b * CC * NN;
    float*      outp = g_xt + (size_t)b * NN * CC;
#pragma unroll
    for (int i = 0; i < 32; i += 8)
        tile[ty + i][tx] = in[(size_t)(c0 + ty + i) * NN + n0 + tx];
    __syncthreads();
#pragma unroll
    for (int i = 0; i < 32; i += 8)
        outp[(size_t)(n0 + ty + i) * CC + c0 + tx] = tile[tx][ty + i];
}

// ---------------------------------------------------------------------------
// Kernel 2: gather + max-relative -> g_rel [B, C, N]
// 32 nodes/block, 256 threads, ~29KB smem -> 6 CTAs/SM (48 warps: L2 latency hidden)
// ---------------------------------------------------------------------------
#define GA_NODES 32
#define SR_S 33

__global__ __launch_bounds__(256) void gather_kernel(const int* __restrict__ edge) {
    __shared__ float srel[CC * SR_S];
    __shared__ int   sj[GA_NODES * KK];
    __shared__ int   si[GA_NODES * KK];

    const int tid = threadIdx.x;
    const int bid = blockIdx.x;
    const int b   = bid >> 8;                 // 256 tiles per batch
    const int n0  = (bid & 255) * GA_NODES;

    const int* ej = edge + ((size_t)b * NN + n0) * KK;
    const int* ei = edge + ((size_t)(BB + b) * NN + n0) * KK;
    for (int t = tid; t < GA_NODES * KK; t += 256) {
        sj[t] = ej[t];
        si[t] = ei[t];
    }
    __syncthreads();

    const float* bx = g_xt + (size_t)b * NN * CC;
    const int wid  = tid >> 5;
    const int lane = tid & 31;
    const int cb   = lane * 2;

    for (int nn = wid; nn < GA_NODES; nn += 8) {   // 4 nodes per warp
        float2 r0 = make_float2(-3.0e38f, -3.0e38f), r1 = r0, r2 = r0;
        const int* sjn = sj + nn * KK;
        const int* sin = si + nn * KK;
#pragma unroll 4
        for (int k = 0; k < KK; k++) {
            const float* pj = bx + (size_t)sjn[k] * CC + cb;
            const float* pi = bx + (size_t)sin[k] * CC + cb;
            float2 a0 = *(const float2*)(pj);       float2 c0v = *(const float2*)(pi);
            float2 a1 = *(const float2*)(pj + 64);  float2 c1v = *(const float2*)(pi + 64);
            float2 a2 = *(const float2*)(pj + 128); float2 c2v = *(const float2*)(pi + 128);
            r0.x = fmaxf(r0.x, a0.x - c0v.x); r0.y = fmaxf(r0.y, a0.y - c0v.y);
            r1.x = fmaxf(r1.x, a1.x - c1v.x); r1.y = fmaxf(r1.y, a1.y - c1v.y);
            r2.x = fmaxf(r2.x, a2.x - c2v.x); r2.y = fmaxf(r2.y, a2.y - c2v.y);
        }
        srel[(cb)       * SR_S + nn] = r0.x;
        srel[(cb + 1)   * SR_S + nn] = r0.y;
        srel[(cb + 64)  * SR_S + nn] = r1.x;
        srel[(cb + 65)  * SR_S + nn] = r1.y;
        srel[(cb + 128) * SR_S + nn] = r2.x;
        srel[(cb + 129) * SR_S + nn] = r2.y;
    }
    __syncthreads();

    // coalesced store: warp = one channel row of 32 floats (128B)
    float* ro = g_rel + (size_t)b * CC * NN + n0;
    for (int t = tid; t < CC * GA_NODES; t += 256) {
        int c = t >> 5, n = t & 31;
        ro[(size_t)c * NN + n] = srel[c * SR_S + n];
    }
}

// ---------------------------------------------------------------------------
// Kernel 3: GEMM  out[b][o][n] = relu( sum_c W[o][c] * y[c][n] + bias[o] )
// y[c] = x[b][c] (c<192) else g_rel[b][c-192]. 64-node tiles, 256 thr, 2 CTA/SM.
// Register-prefetch double buffer on the y chunk; FFMA2 inner loop.
// ---------------------------------------------------------------------------
#define GN 64
#define KC 32
#define NCH (TWOC / KC)      // 12
#define WPD 33

#define YCH_BYTES (KC * GN * 4)                // 8192
#define WSD_OFF   YCH_BYTES
#define GEMM_SMEM (WSD_OFF + COUT * WPD * 8)   // 8192 + 50688 = 58880

__global__ __launch_bounds__(256, 2)
void gemm_kernel(const float* __restrict__ x, const float* __restrict__ W,
                 const float* __restrict__ bias, float* __restrict__ out) {
    extern __shared__ char smem[];
    float*  ych = (float*)smem;                 // y chunk [32 k][64 n]
    float2* wsd = (float2*)(smem + WSD_OFF);    // W chunk duplicated [192 o][33] {w,w}
    ull*    wsq = (ull*)wsd;

    const int tid = threadIdx.x;
    const int bid = blockIdx.x;
    const int b   = bid >> 7;                   // 128 tiles per batch
    const int n0  = (bid & 127) * GN;

    const int oi = tid >> 3;                    // 32 groups x 6 outputs
    const int ni = tid & 7;                     // 8 groups x 8 nodes (4 + 4 @+32)

    const float* xb = x     + (size_t)b * CC * NN + n0;
    const float* rb = g_rel + (size_t)b * CC * NN + n0;

    float bv[6];
#pragma unroll
    for (int m = 0; m < 6; m++) bv[m] = bias[oi * 6 + m];

    ull acc[6][4];
#pragma unroll
    for (int m = 0; m < 6; m++)
#pragma unroll
        for (int p = 0; p < 4; p++) acc[m][p] = 0ULL;

    // y-chunk loader: 512 float4 per chunk, 2 per thread
    const int prow = tid >> 3;                  // wait: 512 f4 / 256 thr -> f = tid*2+j
    (void)prow;
    float4 pf0, pf1;
    {
        int f0 = tid * 2, f1 = tid * 2 + 1;
        const float* s = xb;                    // chunk 0 is x
        pf0 = *(const float4*)(s + (size_t)(f0 >> 4) * NN + (f0 & 15) * 4);
        pf1 = *(const float4*)(s + (size_t)(f1 >> 4) * NN + (f1 & 15) * 4);
    }

    const ull* wp = wsq + oi * 6 * WPD;

    for (int ch = 0; ch < NCH; ch++) {
        // commit prefetched y chunk to smem
        ((float4*)ych)[tid * 2]     = pf0;
        ((float4*)ych)[tid * 2 + 1] = pf1;
        // stage W chunk (duplicated pairs)
        const float* wsrc = W + ch * KC;
        for (int t = tid; t < COUT * KC; t += 256) {
            int o = t >> 5, k = t & 31;
            float v = wsrc[(size_t)o * TWOC + k];
            wsd[o * WPD + k] = make_float2(v, v);
        }
        __syncthreads();

        // prefetch next chunk (global latency overlapped with FMA work below)
        if (ch + 1 < NCH) {
            int c0n = (ch + 1) * KC;
            const float* s = (c0n < CC) ? (xb + (size_t)c0n * NN)
                                        : (rb + (size_t)(c0n - CC) * NN);
            int f0 = tid * 2, f1 = tid * 2 + 1;
            pf0 = *(const float4*)(s + (size_t)(f0 >> 4) * NN + (f0 & 15) * 4);
            pf1 = *(const float4*)(s + (size_t)(f1 >> 4) * NN + (f1 & 15) * 4);
        }

#pragma unroll 8
        for (int kk = 0; kk < KC; kk++) {
            longlong2 qa = *(const longlong2*)(ych + kk * GN + ni * 4);
            longlong2 qb = *(const longlong2*)(ych + kk * GN + 32 + ni * 4);
            ull y2[4] = { (ull)qa.x, (ull)qa.y, (ull)qb.x, (ull)qb.y };
#pragma unroll
            for (int m = 0; m < 6; m++) {
                ull w = wp[m * WPD + kk];
#pragma unroll
                for (int p = 0; p < 4; p++)
                    asm("fma.rn.f32x2 %0, %1, %2, %3;"
                        : "=l"(acc[m][p]) : "l"(w), "l"(y2[p]), "l"(acc[m][p]));
            }
        }
        __syncthreads();
    }

    // epilogue: bias + relu, direct float4 stores (coalesced within warp)
    float* ob = out + (size_t)b * COUT * NN + n0 + ni * 4;
#pragma unroll
    for (int m = 0; m < 6; m++) {
        float4 v0, v1;
        float a, bq;
        asm("mov.b64 {%0, %1}, %2;" : "=f"(a), "=f"(bq) : "l"(acc[m][0]));
        v0.x = fmaxf(a + bv[m], 0.0f); v0.y = fmaxf(bq + bv[m], 0.0f);
        asm("mov.b64 {%0, %1}, %2;" : "=f"(a), "=f"(bq) : "l"(acc[m][1]));
        v0.z = fmaxf(a + bv[m], 0.0f); v0.w = fmaxf(bq + bv[m], 0.0f);
        asm("mov.b64 {%0, %1}, %2;" : "=f"(a), "=f"(bq) : "l"(acc[m][2]));
        v1.x = fmaxf(a + bv[m], 0.0f); v1.y = fmaxf(bq + bv[m], 0.0f);
        asm("mov.b64 {%0, %1}, %2;" : "=f"(a), "=f"(bq) : "l"(acc[m][3]));
        v1.z = fmaxf(a + bv[m], 0.0f); v1.w = fmaxf(bq + bv[m], 0.0f);
        float* op = ob + (size_t)(oi * 6 + m) * NN;
        *(float4*)(op)      = v0;
        *(float4*)(op + 32) = v1;
    }
}

// ---------------------------------------------------------------------------
// Launch
// ---------------------------------------------------------------------------
extern "C" void kernel_launch(void* const* d_in, const int* in_sizes, int n_in,
                              void* d_out, int out_size) {
    const float* x    = (const float*)d_in[0];
    const int*   edge = (const int*)d_in[2];
    const float* W    = (const float*)d_in[3];
    const float* bias = (const float*)d_in[4];
    float*       out  = (float*)d_out;

    cudaFuncSetAttribute(gemm_kernel, cudaFuncAttributeMaxDynamicSharedMemorySize,
                         GEMM_SMEM);

    transpose_kernel<<<dim3(NN / 32, CC / 32, BB), dim3(32, 8)>>>(x);
    gather_kernel<<<BB * (NN / GA_NODES), 256>>>(edge);
    gemm_kernel<<<BB * (NN / GN), 256, GEMM_SMEM>>>(x, W, bias, out);
}

// round 5
// speedup vs baseline: 1.8797x; 1.0348x over previous
#include <cuda_runtime.h>
#include <cstdint>

#define BB 4
#define CC 192
#define NN 8192
#define KK 16
#define COUT 192
#define TWOC 384

typedef unsigned long long ull;

// Scratch: x transposed to [B, N, C]; rel in [B, C, N]; partial GEMM sums.
__device__ float g_xt [(size_t)BB * NN * CC];
__device__ float g_rel[(size_t)BB * CC * NN];
__device__ float g_part[(size_t)BB * COUT * NN];

// ---------------------------------------------------------------------------
// Kernel 1: transpose x [B, C, N] -> g_xt [B, N, C]
// ---------------------------------------------------------------------------
__global__ void transpose_kernel(const float* __restrict__ x) {
    __shared__ float tile[32][33];
    int b  = blockIdx.z;
    int n0 = blockIdx.x * 32;
    int c0 = blockIdx.y * 32;
    int tx = threadIdx.x, ty = threadIdx.y;
    const float* in  = x    + (size_t)b * CC * NN;
    float*      outp = g_xt + (size_t)b * NN * CC;
#pragma unroll
    for (int i = 0; i < 32; i += 8)
        tile[ty + i][tx] = in[(size_t)(c0 + ty + i) * NN + n0 + tx];
    __syncthreads();
#pragma unroll
    for (int i = 0; i < 32; i += 8)
        outp[(size_t)(n0 + ty + i) * CC + c0 + tx] = tile[tx][ty + i];
}

// ---------------------------------------------------------------------------
// Kernel 2: gather + max-relative -> g_rel [B, C, N]
// 32 nodes/block; each warp handles 2 nodes concurrently (2x MLP).
// ---------------------------------------------------------------------------
#define GA_NODES 32
#define SR_S 33

__global__ __launch_bounds__(256) void gather_kernel(const int* __restrict__ edge) {
    __shared__ float srel[CC * SR_S];
    __shared__ int   sj[GA_NODES * KK];
    __shared__ int   si[GA_NODES * KK];

    const int tid = threadIdx.x;
    const int bid = blockIdx.x;
    const int b   = bid >> 8;
    const int n0  = (bid & 255) * GA_NODES;

    const int* ej = edge + ((size_t)b * NN + n0) * KK;
    const int* ei = edge + ((size_t)(BB + b) * NN + n0) * KK;
    for (int t = tid; t < GA_NODES * KK; t += 256) {
        sj[t] = ej[t];
        si[t] = ei[t];
    }
    __syncthreads();

    const float* bx = g_xt + (size_t)b * NN * CC;
    const int wid  = tid >> 5;
    const int lane = tid & 31;
    const int cb   = lane * 2;

#pragma unroll
    for (int t = 0; t < 2; t++) {
        const int nA = wid + t * 16;
        const int nB = nA + 8;
        float2 a0 = make_float2(-3.0e38f, -3.0e38f), a1 = a0, a2 = a0;
        float2 b0 = a0, b1 = a0, b2 = a0;
        const int* sjA = sj + nA * KK; const int* siA = si + nA * KK;
        const int* sjB = sj + nB * KK; const int* siB = si + nB * KK;
#pragma unroll 2
        for (int k = 0; k < KK; k++) {
            const float* pjA = bx + (size_t)sjA[k] * CC + cb;
            const float* piA = bx + (size_t)siA[k] * CC + cb;
            const float* pjB = bx + (size_t)sjB[k] * CC + cb;
            const float* piB = bx + (size_t)siB[k] * CC + cb;
            float2 ja0 = *(const float2*)(pjA);       float2 ia0 = *(const float2*)(piA);
            float2 ja1 = *(const float2*)(pjA + 64);  float2 ia1 = *(const float2*)(piA + 64);
            float2 ja2 = *(const float2*)(pjA + 128); float2 ia2 = *(const float2*)(piA + 128);
            float2 jb0 = *(const float2*)(pjB);       float2 ib0 = *(const float2*)(piB);
            float2 jb1 = *(const float2*)(pjB + 64);  float2 ib1 = *(const float2*)(piB + 64);
            float2 jb2 = *(const float2*)(pjB + 128); float2 ib2 = *(const float2*)(piB + 128);
            a0.x = fmaxf(a0.x, ja0.x - ia0.x); a0.y = fmaxf(a0.y, ja0.y - ia0.y);
            a1.x = fmaxf(a1.x, ja1.x - ia1.x); a1.y = fmaxf(a1.y, ja1.y - ia1.y);
            a2.x = fmaxf(a2.x, ja2.x - ia2.x); a2.y = fmaxf(a2.y, ja2.y - ia2.y);
            b0.x = fmaxf(b0.x, jb0.x - ib0.x); b0.y = fmaxf(b0.y, jb0.y - ib0.y);
            b1.x = fmaxf(b1.x, jb1.x - ib1.x); b1.y = fmaxf(b1.y, jb1.y - ib1.y);
            b2.x = fmaxf(b2.x, jb2.x - ib2.x); b2.y = fmaxf(b2.y, jb2.y - ib2.y);
        }
        srel[(cb)       * SR_S + nA] = a0.x; srel[(cb + 1)   * SR_S + nA] = a0.y;
        srel[(cb + 64)  * SR_S + nA] = a1.x; srel[(cb + 65)  * SR_S + nA] = a1.y;
        srel[(cb + 128) * SR_S + nA] = a2.x; srel[(cb + 129) * SR_S + nA] = a2.y;
        srel[(cb)       * SR_S + nB] = b0.x; srel[(cb + 1)   * SR_S + nB] = b0.y;
        srel[(cb + 64)  * SR_S + nB] = b1.x; srel[(cb + 65)  * SR_S + nB] = b1.y;
        srel[(cb + 128) * SR_S + nB] = b2.x; srel[(cb + 129) * SR_S + nB] = b2.y;
    }
    __syncthreads();

    float* ro = g_rel + (size_t)b * CC * NN + n0;
    for (int t = tid; t < CC * GA_NODES; t += 256) {
        int c = t >> 5, n = t & 31;
        ro[(size_t)c * NN + n] = srel[c * SR_S + n];
    }
}

// ---------------------------------------------------------------------------
// GEMM halves. Common tile: 64 nodes, 256 thr, 2 CTA/SM.
// ---------------------------------------------------------------------------
#define GN 64
#define KC 32
#define NCHH (CC / KC)       // 6 chunks per half
#define WPD 33

#define YCH_BYTES (KC * GN * 4)
#define WSD_OFF   YCH_BYTES
#define GEMM_SMEM (WSD_OFF + COUT * WPD * 8)   // 58880

// Half-GEMM body: accumulates 6 chunks from ysrc with W columns [wc0, wc0+192).
__device__ __forceinline__ void gemm_half(const float* __restrict__ ysrc,
                                          const float* __restrict__ W, int wc0,
                                          int tid, int oi, int ni,
                                          float* ych, float2* wsd, ull acc[6][4]) {
    ull* wsq = (ull*)wsd;
    const ull* wp = wsq + oi * 6 * WPD;

    float4 pf0, pf1;
    {
        int f0 = tid * 2, f1 = tid * 2 + 1;
        pf0 = *(const float4*)(ysrc + (size_t)(f0 >> 4) * NN + (f0 & 15) * 4);
        pf1 = *(const float4*)(ysrc + (size_t)(f1 >> 4) * NN + (f1 & 15) * 4);
    }

    for (int ch = 0; ch < NCHH; ch++) {
        ((float4*)ych)[tid * 2]     = pf0;
        ((float4*)ych)[tid * 2 + 1] = pf1;
        const float* wsrc = W + wc0 + ch * KC;
        for (int t = tid; t < COUT * KC; t += 256) {
            int o = t >> 5, k = t & 31;
            float v = wsrc[(size_t)o * TWOC + k];
            wsd[o * WPD + k] = make_float2(v, v);
        }
        __syncthreads();

        if (ch + 1 < NCHH) {
            const float* s = ysrc + (size_t)(ch + 1) * KC * NN;
            int f0 = tid * 2, f1 = tid * 2 + 1;
            pf0 = *(const float4*)(s + (size_t)(f0 >> 4) * NN + (f0 & 15) * 4);
            pf1 = *(const float4*)(s + (size_t)(f1 >> 4) * NN + (f1 & 15) * 4);
        }

#pragma unroll 8
        for (int kk = 0; kk < KC; kk++) {
            longlong2 qa = *(const longlong2*)(ych + kk * GN + ni * 4);
            longlong2 qb = *(const longlong2*)(ych + kk * GN + 32 + ni * 4);
            ull y2[4] = { (ull)qa.x, (ull)qa.y, (ull)qb.x, (ull)qb.y };
#pragma unroll
            for (int m = 0; m < 6; m++) {
                ull w = wp[m * WPD + kk];
#pragma unroll
                for (int p = 0; p < 4; p++)
                    asm("fma.rn.f32x2 %0, %1, %2, %3;"
                        : "=l"(acc[m][p]) : "l"(w), "l"(y2[p]), "l"(acc[m][p]));
            }
        }
        __syncthreads();
    }
}

// GEMM part 1: y = x (c<192). No gather dependence. Writes raw partials.
__global__ __launch_bounds__(256, 2)
void gemm_x_kernel(const float* __restrict__ x, const float* __restrict__ W) {
    extern __shared__ char smem[];
    float*  ych = (float*)smem;
    float2* wsd = (float2*)(smem + WSD_OFF);

    const int tid = threadIdx.x;
    const int bid = blockIdx.x;
    const int b   = bid >> 7;
    const int n0  = (bid & 127) * GN;
    const int oi  = tid >> 3;
    const int ni  = tid & 7;

    ull acc[6][4];
#pragma unroll
    for (int m = 0; m < 6; m++)
#pragma unroll
        for (int p = 0; p < 4; p++) acc[m][p] = 0ULL;

    gemm_half(x + (size_t)b * CC * NN + n0, W, 0, tid, oi, ni, ych, wsd, acc);

    float* pb = g_part + (size_t)b * COUT * NN + n0 + ni * 4;
#pragma unroll
    for (int m = 0; m < 6; m++) {
        float* op = pb + (size_t)(oi * 6 + m) * NN;
        float4 v0, v1; float a, c;
        asm("mov.b64 {%0, %1}, %2;" : "=f"(a), "=f"(c) : "l"(acc[m][0])); v0.x = a; v0.y = c;
        asm("mov.b64 {%0, %1}, %2;" : "=f"(a), "=f"(c) : "l"(acc[m][1])); v0.z = a; v0.w = c;
        asm("mov.b64 {%0, %1}, %2;" : "=f"(a), "=f"(c) : "l"(acc[m][2])); v1.x = a; v1.y = c;
        asm("mov.b64 {%0, %1}, %2;" : "=f"(a), "=f"(c) : "l"(acc[m][3])); v1.z = a; v1.w = c;
        *(float4*)(op)      = v0;
        *(float4*)(op + 32) = v1;
    }
}

// GEMM part 2: y = rel (c in [192,384)). Adds partial + bias, relu, stores out.
__global__ __launch_bounds__(256, 2)
void gemm_rel_kernel(const float* __restrict__ W, const float* __restrict__ bias,
                     float* __restrict__ out) {
    extern __shared__ char smem[];
    float*  ych = (float*)smem;
    float2* wsd = (float2*)(smem + WSD_OFF);

    const int tid = threadIdx.x;
    const int bid = blockIdx.x;
    const int b   = bid >> 7;
    const int n0  = (bid & 127) * GN;
    const int oi  = tid >> 3;
    const int ni  = tid & 7;

    float bv[6];
#pragma unroll
    for (int m = 0; m < 6; m++) bv[m] = bias[oi * 6 + m];

    ull acc[6][4];
#pragma unroll
    for (int m = 0; m < 6; m++)
#pragma unroll
        for (int p = 0; p < 4; p++) acc[m][p] = 0ULL;

    gemm_half(g_rel + (size_t)b * CC * NN + n0, W, CC, tid, oi, ni, ych, wsd, acc);

    const float* pb = g_part + (size_t)b * COUT * NN + n0 + ni * 4;
    float*       ob = out    + (size_t)b * COUT * NN + n0 + ni * 4;
#pragma unroll
    for (int m = 0; m < 6; m++) {
        const float* pp = pb + (size_t)(oi * 6 + m) * NN;
        float4 p0 = *(const float4*)(pp);
        float4 p1 = *(const float4*)(pp + 32);
        float4 v0, v1; float a, c;
        asm("mov.b64 {%0, %1}, %2;" : "=f"(a), "=f"(c) : "l"(acc[m][0]));
        v0.x = fmaxf(p0.x + a + bv[m], 0.0f); v0.y = fmaxf(p0.y + c + bv[m], 0.0f);
        asm("mov.b64 {%0, %1}, %2;" : "=f"(a), "=f"(c) : "l"(acc[m][1]));
        v0.z = fmaxf(p0.z + a + bv[m], 0.0f); v0.w = fmaxf(p0.w + c + bv[m], 0.0f);
        asm("mov.b64 {%0, %1}, %2;" : "=f"(a), "=f"(c) : "l"(acc[m][2]));
        v1.x = fmaxf(p1.x + a + bv[m], 0.0f); v1.y = fmaxf(p1.y + c + bv[m], 0.0f);
        asm("mov.b64 {%0, %1}, %2;" : "=f"(a), "=f"(c) : "l"(acc[m][3]));
        v1.z = fmaxf(p1.z + a + bv[m], 0.0f); v1.w = fmaxf(p1.w + c + bv[m], 0.0f);
        float* op = ob + (size_t)(oi * 6 + m) * NN;
        *(float4*)(op)      = v0;
        *(float4*)(op + 32) = v1;
    }
}

// ---------------------------------------------------------------------------
// Launch: fork gemm_x onto a side stream, overlapped with transpose+gather.
// ---------------------------------------------------------------------------
extern "C" void kernel_launch(void* const* d_in, const int* in_sizes, int n_in,
                              void* d_out, int out_size) {
    const float* x    = (const float*)d_in[0];
    const int*   edge = (const int*)d_in[2];
    const float* W    = (const float*)d_in[3];
    const float* bias = (const float*)d_in[4];
    float*       out  = (float*)d_out;

    static cudaStream_t s2 = nullptr;
    static cudaEvent_t  eFork = nullptr, eJoin = nullptr;
    if (s2 == nullptr) {
        cudaStreamCreateWithFlags(&s2, cudaStreamNonBlocking);
        cudaEventCreateWithFlags(&eFork, cudaEventDisableTiming);
        cudaEventCreateWithFlags(&eJoin, cudaEventDisableTiming);
        cudaFuncSetAttribute(gemm_x_kernel,
                             cudaFuncAttributeMaxDynamicSharedMemorySize, GEMM_SMEM);
        cudaFuncSetAttribute(gemm_rel_kernel,
                             cudaFuncAttributeMaxDynamicSharedMemorySize, GEMM_SMEM);
    }

    // fork: side stream runs the gather-independent x-half GEMM
    cudaEventRecord(eFork, 0);
    cudaStreamWaitEvent(s2, eFork, 0);
    gemm_x_kernel<<<BB * (NN / GN), 256, GEMM_SMEM, s2>>>(x, W);
    cudaEventRecord(eJoin, s2);

    // main stream: transpose -> gather
    transpose_kernel<<<dim3(NN / 32, CC / 32, BB), dim3(32, 8)>>>(x);
    gather_kernel<<<BB * (NN / GA_NODES), 256>>>(edge);

    // join, then rel-half GEMM + epilogue
    cudaStreamWaitEvent(0, eJoin, 0);
    gemm_rel_kernel<<<BB * (NN / GN), 256, GEMM_SMEM>>>(W, bias, out);
}